// round 14
// baseline (speedup 1.0000x reference)
#include <cuda_runtime.h>
#include <math.h>
#include <stdint.h>

// Problem constants
#define B_   512
#define T_   200
#define D_   256
#define H_   256
#define BT_  (B_ * T_)      // 102400

// Recurrent-kernel geometry
#define RG_  16             // batch rows per cluster
#define NG_  (B_ / RG_)     // 32 clusters
#define CSZ  4              // CTAs per cluster (column split)
#define THREADS_R 512

typedef unsigned long long ull;

// Scratch (device globals; no allocation anywhere)
__device__ float g_Gx[BT_ * 2 * H_];   // [B*T, 512]  x@Wgx + gate_bias
__device__ float g_Cx[BT_ * H_];       // [B*T, 256]  x@Wcx + cand_bias

// SMEM layout (float offsets). Weights are split into 4 k-quarter regions,
// each padded by +4 floats so the 4 ks-lanes' bases sit on distinct bank
// quartets (region size ≡ 4 mod 32).
#define OFF_WG 0
#define WG_REG 8196        // 16 kb * 512 + 4
#define OFF_WC 32784       // 4 * WG_REG
#define WC_REG 4100        // 16 kb * 256 + 4
#define OFF_H  49184       // 32784 + 4*4100 (multiple of 32)
#define OFF_RH 53280       // OFF_H + 4096
#define SMEM_FLOATS 57376
#define SMEM_BYTES (SMEM_FLOATS * 4)   // 229504 B (<= 232448 max)

// h storage swizzle: within a row, XOR the float index by
//   (row-group)<<3  (quartets 0/2/4/6)  and  (k bit6)<<2  (quartet +1)
// so the 8 lanes of one LSU phase (rg 0..3 x ks-LSB 0..1) hit 8 distinct
// 16B bank quartets. XOR bits are >=2, so 4-aligned chunks stay contiguous.
__device__ __forceinline__ int hswz(int row, int k) {
    return row * 256 + (k ^ (((row >> 2) & 3) << 3) ^ (((k >> 6) & 1) << 2));
}

// ---- Blackwell packed fp32x2 helpers ----
__device__ __forceinline__ ull fma2(ull a, ull b, ull c) {
    ull d; asm("fma.rn.f32x2 %0, %1, %2, %3;" : "=l"(d) : "l"(a), "l"(b), "l"(c));
    return d;
}
__device__ __forceinline__ ull pack2(float lo, float hi) {
    ull d; asm("mov.b64 %0, {%1, %2};" : "=l"(d) : "f"(lo), "f"(hi));
    return d;
}
__device__ __forceinline__ float2 unpack2(ull v) {
    float2 r; asm("mov.b64 {%0, %1}, %2;" : "=f"(r.x), "=f"(r.y) : "l"(v));
    return r;
}
__device__ __forceinline__ float sigmoid_f(float x) { return 1.f / (1.f + __expf(-x)); }
__device__ __forceinline__ float tanh_f(float x)    { return 2.f / (1.f + __expf(-2.f * x)) - 1.f; }

__device__ __forceinline__ uint32_t smem_u32(const void* p) {
    uint32_t a;
    asm("{ .reg .u64 t; cvta.to.shared.u64 t, %1; cvt.u32.u64 %0, t; }" : "=r"(a) : "l"(p));
    return a;
}
__device__ __forceinline__ uint32_t ctarank() {
    uint32_t r; asm("mov.u32 %0, %%cluster_ctarank;" : "=r"(r));
    return r;
}
__device__ __forceinline__ uint32_t mapa_sh(uint32_t addr, uint32_t rank) {
    uint32_t r; asm("mapa.shared::cluster.u32 %0, %1, %2;" : "=r"(r) : "r"(addr), "r"(rank));
    return r;
}
__device__ __forceinline__ void st_cluster_b64(uint32_t addr, ull v) {
    asm volatile("st.shared::cluster.b64 [%0], %1;" :: "r"(addr), "l"(v) : "memory");
}
#define CLUSTER_SYNC() do { \
    asm volatile("barrier.cluster.arrive.aligned;" ::: "memory"); \
    asm volatile("barrier.cluster.wait.aligned;" ::: "memory");   \
} while (0)

// ---------------------------------------------------------------------------
// Precompute GEMM (unchanged)
// ---------------------------------------------------------------------------
#define GBM 128
#define GBN 64
#define GBK 16

__global__ __launch_bounds__(256) void gemm_precompute(
    const float* __restrict__ X,
    const float* __restrict__ W,
    const float* __restrict__ bias,
    const int*   __restrict__ seqlen,
    int N)
{
    const int r0 = blockIdx.x * GBM;
    const int n0 = blockIdx.y * GBN;

    {
        int b0 = r0 / T_;
        int b1 = (r0 + GBM - 1) / T_;
        bool needed = false;
        for (int b = b0; b <= b1; ++b) {
            int tstart = r0 - b * T_;
            if (tstart < 0) tstart = 0;
            if (tstart < seqlen[b]) { needed = true; break; }
        }
        if (!needed) return;
    }

    float* __restrict__ C = (N == 2 * H_) ? g_Gx : g_Cx;

    __shared__ float As[GBK][GBM];
    __shared__ float Bs[GBK][GBN];

    const int tid = threadIdx.x;
    const int am  = tid >> 2;
    const int ak  = (tid & 3) * 4;
    const int bk  = tid >> 4;
    const int bn  = (tid & 15) * 4;
    const int tm  = (tid >> 4) * 8;
    const int tn  = (tid & 15) * 4;

    ull acc2[4][4];
#pragma unroll
    for (int p = 0; p < 4; ++p)
#pragma unroll
        for (int j = 0; j < 4; ++j) acc2[p][j] = 0ull;

    for (int kt = 0; kt < D_; kt += GBK) {
        float4 a0 = *(const float4*)(X + (size_t)(r0 + am) * D_ + kt + ak);
        float4 a1 = *(const float4*)(X + (size_t)(r0 + am + 64) * D_ + kt + ak);
        As[ak + 0][am] = a0.x;  As[ak + 1][am] = a0.y;
        As[ak + 2][am] = a0.z;  As[ak + 3][am] = a0.w;
        As[ak + 0][am + 64] = a1.x;  As[ak + 1][am + 64] = a1.y;
        As[ak + 2][am + 64] = a1.z;  As[ak + 3][am + 64] = a1.w;
        *(float4*)&Bs[bk][bn] = *(const float4*)(W + (size_t)(kt + bk) * N + n0 + bn);
        __syncthreads();

#pragma unroll
        for (int k = 0; k < GBK; ++k) {
            ulonglong2 a01 = *(const ulonglong2*)&As[k][tm];
            ulonglong2 a23 = *(const ulonglong2*)&As[k][tm + 4];
            float4 bq = *(const float4*)&Bs[k][tn];
            ull ap[4] = { a01.x, a01.y, a23.x, a23.y };
            ull bp[4] = { pack2(bq.x, bq.x), pack2(bq.y, bq.y),
                          pack2(bq.z, bq.z), pack2(bq.w, bq.w) };
#pragma unroll
            for (int p = 0; p < 4; ++p)
#pragma unroll
                for (int j = 0; j < 4; ++j)
                    acc2[p][j] = fma2(ap[p], bp[j], acc2[p][j]);
        }
        __syncthreads();
    }

    float4 bv = *(const float4*)(bias + n0 + tn);
#pragma unroll
    for (int p = 0; p < 4; ++p) {
        float2 c0 = unpack2(acc2[p][0]);
        float2 c1 = unpack2(acc2[p][1]);
        float2 c2 = unpack2(acc2[p][2]);
        float2 c3 = unpack2(acc2[p][3]);
        int row0 = r0 + tm + 2 * p;
        float4 o0 = make_float4(c0.x + bv.x, c1.x + bv.y, c2.x + bv.z, c3.x + bv.w);
        float4 o1 = make_float4(c0.y + bv.x, c1.y + bv.y, c2.y + bv.z, c3.y + bv.w);
        *(float4*)(C + (size_t)row0 * N + n0 + tn) = o0;
        *(float4*)(C + (size_t)(row0 + 1) * N + n0 + tn) = o1;
    }
}

// ---------------------------------------------------------------------------
// Recurrent kernel: 32 clusters x 4 CTAs, 16 rows/cluster, SMEM weights.
// 4 cols x 4 rows x k-quarter per thread: every kb does 8 LDS.128 feeding
// 32 fma2 (crossbar wavefronts/step: 8192 phase1 + 4096 phase2 vs 31K in R9).
// Lane map: cp = lane>>4 (col quad within warp), ks = (lane>>2)&3 (k quarter),
// rg = lane&3 (row quad). Warp w covers gate cols [w*8, w*8+8) (w<8 r-cols,
// w>=8 u-cols). Partials reduced with 2 shfl.bfly rounds; ks==0 lanes own the
// epilogue. Two cluster barriers per step (R9 structure kept).
// ---------------------------------------------------------------------------
__global__ __launch_bounds__(THREADS_R, 1) __cluster_dims__(CSZ, 1, 1)
void gru_recurrent(const float* __restrict__ Wg,   // [512, 512]
                   const float* __restrict__ Wc,   // [512, 256]
                   const int*   __restrict__ seqlen,
                   float* __restrict__ out)        // [B, T, 256]
{
    extern __shared__ float sm[];
    const int tid  = threadIdx.x;
    const int lane = tid & 31;
    const int w    = tid >> 5;
    const uint32_t c = ctarank();
    const int b0 = (blockIdx.x / CSZ) * RG_;

    const int rg = lane & 3;
    const int ks = (lane >> 2) & 3;
    const int cp = lane >> 4;
    const int rbase = rg * 4;
    const bool isR = (w < 8);
    const int jquad = w * 8 + cp * 4;                 // [0,128)
    const int jc    = isR ? jquad : (jquad - 64);     // [0,64)
    const int gcolb = isR ? ((int)c * 64 + jquad) : (256 + (int)c * 64 + jc);
    const int ccolb = (int)c * 64 + jc;
    const bool ks0  = (ks == 0);

    // ---- load weight slices into SMEM (k-quarter regions, padded) ----
    for (int idx = tid; idx < 64 * 128; idx += THREADS_R) {
        int kb = idx >> 7, jj = idx & 127;
        int col = (jj < 64) ? ((int)c * 64 + jj) : (256 + (int)c * 64 + (jj - 64));
        float* dst = sm + OFF_WG + (kb >> 4) * WG_REG + (kb & 15) * 512 + jj * 4;
#pragma unroll
        for (int i = 0; i < 4; ++i)
            dst[i] = Wg[(256 + kb * 4 + i) * 512 + col];
    }
    for (int idx = tid; idx < 64 * 64; idx += THREADS_R) {
        int kb = idx >> 6, jj = idx & 63;
        int col = (int)c * 64 + jj;
        float* dst = sm + OFF_WC + (kb >> 4) * WC_REG + (kb & 15) * 256 + jj * 4;
#pragma unroll
        for (int i = 0; i < 4; ++i)
            dst[i] = Wc[(256 + kb * 4 + i) * 256 + col];
    }
    for (int i = tid; i < 16 * 256; i += THREADS_R) sm[OFF_H + i] = 0.f;

    int tmax = 0;
    for (int rr = 0; rr < RG_; ++rr) tmax = max(tmax, seqlen[b0 + rr]);
    int lenv[4];
#pragma unroll
    for (int rr = 0; rr < 4; ++rr) lenv[rr] = seqlen[b0 + rbase + rr];

    __syncthreads();
    CLUSTER_SYNC();

    const uint32_t smaddr = smem_u32(sm);
    const float* __restrict__ wgp = sm + OFF_WG + ks * WG_REG + jquad * 4;
    const float* __restrict__ wcp = sm + OFF_WC + ks * WC_REG + jc * 4;
    const int xorc = (rg << 3) | ((ks & 1) << 2);
    const float* __restrict__ hb = sm + OFF_H + rbase * 256 + ks * 64;
    const float* __restrict__ rb = sm + OFF_RH + rbase * 256 + ks * 64;

    for (int t = 0; t < tmax; ++t) {
        // ============ phase 1 GEMV: 4 gate cols x 4 rows x k-quarter ========
        ull acc[16];
#pragma unroll
        for (int x = 0; x < 16; ++x) acc[x] = 0ull;
#pragma unroll
        for (int i = 0; i < 16; ++i) {
            const float* wp = wgp + i * 512;
            ulonglong2 w0 = *(const ulonglong2*)(wp);
            ulonglong2 w1 = *(const ulonglong2*)(wp + 4);
            ulonglong2 w2 = *(const ulonglong2*)(wp + 8);
            ulonglong2 w3 = *(const ulonglong2*)(wp + 12);
            const float* hp = hb + ((i * 4) ^ xorc);
            ulonglong2 h0 = *(const ulonglong2*)(hp);
            ulonglong2 h1 = *(const ulonglong2*)(hp + 256);
            ulonglong2 h2 = *(const ulonglong2*)(hp + 512);
            ulonglong2 h3 = *(const ulonglong2*)(hp + 768);
            acc[0]  = fma2(w0.x, h0.x, acc[0]);   acc[0]  = fma2(w0.y, h0.y, acc[0]);
            acc[1]  = fma2(w0.x, h1.x, acc[1]);   acc[1]  = fma2(w0.y, h1.y, acc[1]);
            acc[2]  = fma2(w0.x, h2.x, acc[2]);   acc[2]  = fma2(w0.y, h2.y, acc[2]);
            acc[3]  = fma2(w0.x, h3.x, acc[3]);   acc[3]  = fma2(w0.y, h3.y, acc[3]);
            acc[4]  = fma2(w1.x, h0.x, acc[4]);   acc[4]  = fma2(w1.y, h0.y, acc[4]);
            acc[5]  = fma2(w1.x, h1.x, acc[5]);   acc[5]  = fma2(w1.y, h1.y, acc[5]);
            acc[6]  = fma2(w1.x, h2.x, acc[6]);   acc[6]  = fma2(w1.y, h2.y, acc[6]);
            acc[7]  = fma2(w1.x, h3.x, acc[7]);   acc[7]  = fma2(w1.y, h3.y, acc[7]);
            acc[8]  = fma2(w2.x, h0.x, acc[8]);   acc[8]  = fma2(w2.y, h0.y, acc[8]);
            acc[9]  = fma2(w2.x, h1.x, acc[9]);   acc[9]  = fma2(w2.y, h1.y, acc[9]);
            acc[10] = fma2(w2.x, h2.x, acc[10]);  acc[10] = fma2(w2.y, h2.y, acc[10]);
            acc[11] = fma2(w2.x, h3.x, acc[11]);  acc[11] = fma2(w2.y, h3.y, acc[11]);
            acc[12] = fma2(w3.x, h0.x, acc[12]);  acc[12] = fma2(w3.y, h0.y, acc[12]);
            acc[13] = fma2(w3.x, h1.x, acc[13]);  acc[13] = fma2(w3.y, h1.y, acc[13]);
            acc[14] = fma2(w3.x, h2.x, acc[14]);  acc[14] = fma2(w3.y, h2.y, acc[14]);
            acc[15] = fma2(w3.x, h3.x, acc[15]);  acc[15] = fma2(w3.y, h3.y, acc[15]);
        }
        float f[16];
#pragma unroll
        for (int x = 0; x < 16; ++x) { float2 v = unpack2(acc[x]); f[x] = v.x + v.y; }
#pragma unroll
        for (int x = 0; x < 16; ++x) f[x] += __shfl_xor_sync(0xffffffffu, f[x], 4);
#pragma unroll
        for (int x = 0; x < 16; ++x) f[x] += __shfl_xor_sync(0xffffffffu, f[x], 8);

        // gates + r*h publish (ks==0 lanes only; loads deferred past GEMV to
        // keep GEMV register pressure low)
        float g[16];
        if (ks0) {
#pragma unroll
            for (int rr = 0; rr < 4; ++rr) {
                float4 G = *(const float4*)(g_Gx +
                    ((size_t)(b0 + rbase + rr) * T_ + t) * 512 + gcolb);
                g[0 + rr]  = sigmoid_f(f[0 + rr]  + G.x);
                g[4 + rr]  = sigmoid_f(f[4 + rr]  + G.y);
                g[8 + rr]  = sigmoid_f(f[8 + rr]  + G.z);
                g[12 + rr] = sigmoid_f(f[12 + rr] + G.w);
            }
            if (isR) {
#pragma unroll
                for (int rr = 0; rr < 4; ++rr) {
                    int hx = hswz(rbase + rr, ccolb);
                    float4 ho = *(const float4*)(sm + OFF_H + hx);
                    ull lo = pack2(g[0 + rr] * ho.x, g[4 + rr]  * ho.y);
                    ull hi = pack2(g[8 + rr] * ho.z, g[12 + rr] * ho.w);
                    uint32_t la = smaddr + (uint32_t)(OFF_RH + hx) * 4;
#pragma unroll
                    for (uint32_t rk = 0; rk < CSZ; ++rk) {
                        uint32_t ra = mapa_sh(la, rk);
                        st_cluster_b64(ra, lo);
                        st_cluster_b64(ra + 8, hi);
                    }
                }
            }
        }
        CLUSTER_SYNC();   // A: RH complete everywhere; all H reads done

        // ============ phase 2 (u-warps): cand GEMV over RH; blend ===========
        if (!isR) {
            ull a2[16];
#pragma unroll
            for (int x = 0; x < 16; ++x) a2[x] = 0ull;
#pragma unroll
            for (int i = 0; i < 16; ++i) {
                const float* wp = wcp + i * 256;
                ulonglong2 w0 = *(const ulonglong2*)(wp);
                ulonglong2 w1 = *(const ulonglong2*)(wp + 4);
                ulonglong2 w2 = *(const ulonglong2*)(wp + 8);
                ulonglong2 w3 = *(const ulonglong2*)(wp + 12);
                const float* hp = rb + ((i * 4) ^ xorc);
                ulonglong2 h0 = *(const ulonglong2*)(hp);
                ulonglong2 h1 = *(const ulonglong2*)(hp + 256);
                ulonglong2 h2 = *(const ulonglong2*)(hp + 512);
                ulonglong2 h3 = *(const ulonglong2*)(hp + 768);
                a2[0]  = fma2(w0.x, h0.x, a2[0]);   a2[0]  = fma2(w0.y, h0.y, a2[0]);
                a2[1]  = fma2(w0.x, h1.x, a2[1]);   a2[1]  = fma2(w0.y, h1.y, a2[1]);
                a2[2]  = fma2(w0.x, h2.x, a2[2]);   a2[2]  = fma2(w0.y, h2.y, a2[2]);
                a2[3]  = fma2(w0.x, h3.x, a2[3]);   a2[3]  = fma2(w0.y, h3.y, a2[3]);
                a2[4]  = fma2(w1.x, h0.x, a2[4]);   a2[4]  = fma2(w1.y, h0.y, a2[4]);
                a2[5]  = fma2(w1.x, h1.x, a2[5]);   a2[5]  = fma2(w1.y, h1.y, a2[5]);
                a2[6]  = fma2(w1.x, h2.x, a2[6]);   a2[6]  = fma2(w1.y, h2.y, a2[6]);
                a2[7]  = fma2(w1.x, h3.x, a2[7]);   a2[7]  = fma2(w1.y, h3.y, a2[7]);
                a2[8]  = fma2(w2.x, h0.x, a2[8]);   a2[8]  = fma2(w2.y, h0.y, a2[8]);
                a2[9]  = fma2(w2.x, h1.x, a2[9]);   a2[9]  = fma2(w2.y, h1.y, a2[9]);
                a2[10] = fma2(w2.x, h2.x, a2[10]);  a2[10] = fma2(w2.y, h2.y, a2[10]);
                a2[11] = fma2(w2.x, h3.x, a2[11]);  a2[11] = fma2(w2.y, h3.y, a2[11]);
                a2[12] = fma2(w3.x, h0.x, a2[12]);  a2[12] = fma2(w3.y, h0.y, a2[12]);
                a2[13] = fma2(w3.x, h1.x, a2[13]);  a2[13] = fma2(w3.y, h1.y, a2[13]);
                a2[14] = fma2(w3.x, h2.x, a2[14]);  a2[14] = fma2(w3.y, h2.y, a2[14]);
                a2[15] = fma2(w3.x, h3.x, a2[15]);  a2[15] = fma2(w3.y, h3.y, a2[15]);
            }
            float f2[16];
#pragma unroll
            for (int x = 0; x < 16; ++x) { float2 v = unpack2(a2[x]); f2[x] = v.x + v.y; }
#pragma unroll
            for (int x = 0; x < 16; ++x) f2[x] += __shfl_xor_sync(0xffffffffu, f2[x], 4);
#pragma unroll
            for (int x = 0; x < 16; ++x) f2[x] += __shfl_xor_sync(0xffffffffu, f2[x], 8);

            if (ks0) {
#pragma unroll
                for (int rr = 0; rr < 4; ++rr) {
                    float4 X = *(const float4*)(g_Cx +
                        ((size_t)(b0 + rbase + rr) * T_ + t) * 256 + ccolb);
                    int hx = hswz(rbase + rr, ccolb);
                    float4 ho = *(const float4*)(sm + OFF_H + hx);  // old h
                    bool valid = (t < lenv[rr]);
                    float c0 = tanh_f(f2[0 + rr]  + X.x);
                    float c1 = tanh_f(f2[4 + rr]  + X.y);
                    float c2 = tanh_f(f2[8 + rr]  + X.z);
                    float c3 = tanh_f(f2[12 + rr] + X.w);
                    float n0 = g[0 + rr]  * ho.x + (1.f - g[0 + rr])  * c0;
                    float n1 = g[4 + rr]  * ho.y + (1.f - g[4 + rr])  * c1;
                    float n2 = g[8 + rr]  * ho.z + (1.f - g[8 + rr])  * c2;
                    float n3 = g[12 + rr] * ho.w + (1.f - g[12 + rr]) * c3;
                    float4 ov = valid ? make_float4(n0, n1, n2, n3)
                                      : make_float4(0.f, 0.f, 0.f, 0.f);
                    *(float4*)(out + ((size_t)(b0 + rbase + rr) * T_ + t) * 256
                               + ccolb) = ov;
                    ull lo = valid ? pack2(n0, n1) : pack2(ho.x, ho.y);
                    ull hi = valid ? pack2(n2, n3) : pack2(ho.z, ho.w);
                    uint32_t la = smaddr + (uint32_t)(OFF_H + hx) * 4;
#pragma unroll
                    for (uint32_t rk = 0; rk < CSZ; ++rk) {
                        uint32_t ra = mapa_sh(la, rk);
                        st_cluster_b64(ra, lo);
                        st_cluster_b64(ra + 8, hi);
                    }
                }
            }
        }
        CLUSTER_SYNC();   // B: new h complete everywhere; RH reads done
    }

    // zero-fill tail t in [tmax, 200): CTA c covers rows [c*4, c*4+4)
    for (int t = tmax; t < T_; ++t) {
#pragma unroll
        for (int q = 0; q < 2; ++q) {
            int cell = q * 512 + tid;            // 0..1023
            int row  = (int)c * 4 + (cell >> 8);
            int col  = cell & 255;
            out[((size_t)(b0 + row) * T_ + t) * 256 + col] = 0.f;
        }
    }
}

// ---------------------------------------------------------------------------
extern "C" void kernel_launch(void* const* d_in, const int* in_sizes, int n_in,
                              void* d_out, int out_size)
{
    const float* X  = (const float*)d_in[0];   // [512, 200, 256]
    const int*   L  = (const int*)  d_in[1];   // [512, 1]
    const float* Wg = (const float*)d_in[2];   // [512, 512]
    const float* bg = (const float*)d_in[3];   // [512]
    const float* Wc = (const float*)d_in[4];   // [512, 256]
    const float* bc = (const float*)d_in[5];   // [256]
    float* out = (float*)d_out;                // [512, 200, 256]

    // Input projections (parallel, independent of recurrence)
    gemm_precompute<<<dim3(BT_ / GBM, (2 * H_) / GBN), 256>>>(X, Wg, bg, L, 2 * H_);
    gemm_precompute<<<dim3(BT_ / GBM, H_ / GBN),       256>>>(X, Wc, bc, L, H_);

    // Sequential scan: 32 clusters x 4 CTAs, SMEM-resident weights
    cudaFuncSetAttribute(gru_recurrent,
                         cudaFuncAttributeMaxDynamicSharedMemorySize, SMEM_BYTES);
    gru_recurrent<<<NG_ * CSZ, THREADS_R, SMEM_BYTES>>>(Wg, Wc, L, out);
}

// round 15
// speedup vs baseline: 1.0411x; 1.0411x over previous
#include <cuda_runtime.h>
#include <math.h>
#include <stdint.h>

// Problem constants
#define B_   512
#define T_   200
#define D_   256
#define H_   256
#define BT_  (B_ * T_)      // 102400

// Recurrent-kernel geometry
#define RG_  16             // batch rows per cluster
#define NG_  (B_ / RG_)     // 32 clusters
#define CSZ  4              // CTAs per cluster (column split)
#define THREADS_R 512

typedef unsigned long long ull;

// Scratch (device globals; no allocation anywhere)
__device__ float g_Gx[BT_ * 2 * H_];   // [B*T, 512]  x@Wgx + gate_bias
__device__ float g_Cx[BT_ * H_];       // [B*T, 256]  x@Wcx + cand_bias

// SMEM layout (float offsets). Weights are split into 4 k-quarter regions,
// each padded by +4 floats so the 4 ks-lanes' bases sit on distinct bank
// quartets (region size ≡ 4 mod 32).
#define OFF_WG 0
#define WG_REG 8196        // 16 kb * 512 + 4
#define OFF_WC 32784       // 4 * WG_REG
#define WC_REG 4100        // 16 kb * 256 + 4
#define OFF_H  49184       // 32784 + 4*4100 (multiple of 32)
#define OFF_RH 53280       // OFF_H + 4096
#define SMEM_FLOATS 57376
#define SMEM_BYTES (SMEM_FLOATS * 4)   // 229504 B (<= 232448 max)

// h storage swizzle: within a row, XOR the float index by
//   (row-group)<<3  (quartets 0/2/4/6)  and  (k bit6)<<2  (quartet +1)
// so the 8 lanes of one LSU phase (rg 0..3 x ks-LSB 0..1) hit 8 distinct
// 16B bank quartets. XOR bits are >=2, so 4-aligned chunks stay contiguous.
__device__ __forceinline__ int hswz(int row, int k) {
    return row * 256 + (k ^ (((row >> 2) & 3) << 3) ^ (((k >> 6) & 1) << 2));
}

// ---- Blackwell packed fp32x2 helpers ----
__device__ __forceinline__ ull fma2(ull a, ull b, ull c) {
    ull d; asm("fma.rn.f32x2 %0, %1, %2, %3;" : "=l"(d) : "l"(a), "l"(b), "l"(c));
    return d;
}
__device__ __forceinline__ ull pack2(float lo, float hi) {
    ull d; asm("mov.b64 %0, {%1, %2};" : "=l"(d) : "f"(lo), "f"(hi));
    return d;
}
__device__ __forceinline__ float2 unpack2(ull v) {
    float2 r; asm("mov.b64 {%0, %1}, %2;" : "=f"(r.x), "=f"(r.y) : "l"(v));
    return r;
}
__device__ __forceinline__ float sigmoid_f(float x) { return 1.f / (1.f + __expf(-x)); }
__device__ __forceinline__ float tanh_f(float x)    { return 2.f / (1.f + __expf(-2.f * x)) - 1.f; }

__device__ __forceinline__ uint32_t smem_u32(const void* p) {
    uint32_t a;
    asm("{ .reg .u64 t; cvta.to.shared.u64 t, %1; cvt.u32.u64 %0, t; }" : "=r"(a) : "l"(p));
    return a;
}
__device__ __forceinline__ uint32_t ctarank() {
    uint32_t r; asm("mov.u32 %0, %%cluster_ctarank;" : "=r"(r));
    return r;
}
__device__ __forceinline__ uint32_t mapa_sh(uint32_t addr, uint32_t rank) {
    uint32_t r; asm("mapa.shared::cluster.u32 %0, %1, %2;" : "=r"(r) : "r"(addr), "r"(rank));
    return r;
}
__device__ __forceinline__ void st_cluster_b64(uint32_t addr, ull v) {
    asm volatile("st.shared::cluster.b64 [%0], %1;" :: "r"(addr), "l"(v) : "memory");
}
#define CLUSTER_SYNC() do { \
    asm volatile("barrier.cluster.arrive.aligned;" ::: "memory"); \
    asm volatile("barrier.cluster.wait.aligned;" ::: "memory");   \
} while (0)

// ---------------------------------------------------------------------------
// Precompute GEMM (unchanged)
// ---------------------------------------------------------------------------
#define GBM 128
#define GBN 64
#define GBK 16

__global__ __launch_bounds__(256) void gemm_precompute(
    const float* __restrict__ X,
    const float* __restrict__ W,
    const float* __restrict__ bias,
    const int*   __restrict__ seqlen,
    int N)
{
    const int r0 = blockIdx.x * GBM;
    const int n0 = blockIdx.y * GBN;

    {
        int b0 = r0 / T_;
        int b1 = (r0 + GBM - 1) / T_;
        bool needed = false;
        for (int b = b0; b <= b1; ++b) {
            int tstart = r0 - b * T_;
            if (tstart < 0) tstart = 0;
            if (tstart < seqlen[b]) { needed = true; break; }
        }
        if (!needed) return;
    }

    float* __restrict__ C = (N == 2 * H_) ? g_Gx : g_Cx;

    __shared__ float As[GBK][GBM];
    __shared__ float Bs[GBK][GBN];

    const int tid = threadIdx.x;
    const int am  = tid >> 2;
    const int ak  = (tid & 3) * 4;
    const int bk  = tid >> 4;
    const int bn  = (tid & 15) * 4;
    const int tm  = (tid >> 4) * 8;
    const int tn  = (tid & 15) * 4;

    ull acc2[4][4];
#pragma unroll
    for (int p = 0; p < 4; ++p)
#pragma unroll
        for (int j = 0; j < 4; ++j) acc2[p][j] = 0ull;

    for (int kt = 0; kt < D_; kt += GBK) {
        float4 a0 = *(const float4*)(X + (size_t)(r0 + am) * D_ + kt + ak);
        float4 a1 = *(const float4*)(X + (size_t)(r0 + am + 64) * D_ + kt + ak);
        As[ak + 0][am] = a0.x;  As[ak + 1][am] = a0.y;
        As[ak + 2][am] = a0.z;  As[ak + 3][am] = a0.w;
        As[ak + 0][am + 64] = a1.x;  As[ak + 1][am + 64] = a1.y;
        As[ak + 2][am + 64] = a1.z;  As[ak + 3][am + 64] = a1.w;
        *(float4*)&Bs[bk][bn] = *(const float4*)(W + (size_t)(kt + bk) * N + n0 + bn);
        __syncthreads();

#pragma unroll
        for (int k = 0; k < GBK; ++k) {
            ulonglong2 a01 = *(const ulonglong2*)&As[k][tm];
            ulonglong2 a23 = *(const ulonglong2*)&As[k][tm + 4];
            float4 bq = *(const float4*)&Bs[k][tn];
            ull ap[4] = { a01.x, a01.y, a23.x, a23.y };
            ull bp[4] = { pack2(bq.x, bq.x), pack2(bq.y, bq.y),
                          pack2(bq.z, bq.z), pack2(bq.w, bq.w) };
#pragma unroll
            for (int p = 0; p < 4; ++p)
#pragma unroll
                for (int j = 0; j < 4; ++j)
                    acc2[p][j] = fma2(ap[p], bp[j], acc2[p][j]);
        }
        __syncthreads();
    }

    float4 bv = *(const float4*)(bias + n0 + tn);
#pragma unroll
    for (int p = 0; p < 4; ++p) {
        float2 c0 = unpack2(acc2[p][0]);
        float2 c1 = unpack2(acc2[p][1]);
        float2 c2 = unpack2(acc2[p][2]);
        float2 c3 = unpack2(acc2[p][3]);
        int row0 = r0 + tm + 2 * p;
        float4 o0 = make_float4(c0.x + bv.x, c1.x + bv.y, c2.x + bv.z, c3.x + bv.w);
        float4 o1 = make_float4(c0.y + bv.x, c1.y + bv.y, c2.y + bv.z, c3.y + bv.w);
        *(float4*)(C + (size_t)row0 * N + n0 + tn) = o0;
        *(float4*)(C + (size_t)(row0 + 1) * N + n0 + tn) = o1;
    }
}

// ---------------------------------------------------------------------------
// Recurrent kernel: 32 clusters x 4 CTAs, 16 rows/cluster, SMEM weights.
// 4 cols x 4 rows x k-quarter per thread: every kb does 8 LDS.128 feeding
// 32 fma2 (crossbar wavefronts/step: 8192 phase1 + 4096 phase2 vs 31K in R9).
// Lane map: cp = lane>>4 (col quad within warp), ks = (lane>>2)&3 (k quarter),
// rg = lane&3 (row quad). Warp w covers gate cols [w*8, w*8+8) (w<8 r-cols,
// w>=8 u-cols). Partials reduced with 2 shfl.bfly rounds; ks==0 lanes own the
// epilogue. Two cluster barriers per step (R9 structure kept).
// ---------------------------------------------------------------------------
__global__ __launch_bounds__(THREADS_R, 1) __cluster_dims__(CSZ, 1, 1)
void gru_recurrent(const float* __restrict__ Wg,   // [512, 512]
                   const float* __restrict__ Wc,   // [512, 256]
                   const int*   __restrict__ seqlen,
                   float* __restrict__ out)        // [B, T, 256]
{
    extern __shared__ float sm[];
    const int tid  = threadIdx.x;
    const int lane = tid & 31;
    const int w    = tid >> 5;
    const uint32_t c = ctarank();
    const int b0 = (blockIdx.x / CSZ) * RG_;

    const int rg = lane & 3;
    const int ks = (lane >> 2) & 3;
    const int cp = lane >> 4;
    const int rbase = rg * 4;
    const bool isR = (w < 8);
    const int jquad = w * 8 + cp * 4;                 // [0,128)
    const int jc    = isR ? jquad : (jquad - 64);     // [0,64)
    const int gcolb = isR ? ((int)c * 64 + jquad) : (256 + (int)c * 64 + jc);
    const int ccolb = (int)c * 64 + jc;
    const bool ks0  = (ks == 0);

    // ---- load weight slices into SMEM (k-quarter regions, padded) ----
    for (int idx = tid; idx < 64 * 128; idx += THREADS_R) {
        int kb = idx >> 7, jj = idx & 127;
        int col = (jj < 64) ? ((int)c * 64 + jj) : (256 + (int)c * 64 + (jj - 64));
        float* dst = sm + OFF_WG + (kb >> 4) * WG_REG + (kb & 15) * 512 + jj * 4;
#pragma unroll
        for (int i = 0; i < 4; ++i)
            dst[i] = Wg[(256 + kb * 4 + i) * 512 + col];
    }
    for (int idx = tid; idx < 64 * 64; idx += THREADS_R) {
        int kb = idx >> 6, jj = idx & 63;
        int col = (int)c * 64 + jj;
        float* dst = sm + OFF_WC + (kb >> 4) * WC_REG + (kb & 15) * 256 + jj * 4;
#pragma unroll
        for (int i = 0; i < 4; ++i)
            dst[i] = Wc[(256 + kb * 4 + i) * 256 + col];
    }
    for (int i = tid; i < 16 * 256; i += THREADS_R) sm[OFF_H + i] = 0.f;

    int tmax = 0;
    for (int rr = 0; rr < RG_; ++rr) tmax = max(tmax, seqlen[b0 + rr]);
    int lenv[4];
#pragma unroll
    for (int rr = 0; rr < 4; ++rr) lenv[rr] = seqlen[b0 + rbase + rr];

    __syncthreads();
    CLUSTER_SYNC();

    const uint32_t smaddr = smem_u32(sm);
    const float* __restrict__ wgp = sm + OFF_WG + ks * WG_REG + jquad * 4;
    const float* __restrict__ wcp = sm + OFF_WC + ks * WC_REG + jc * 4;
    const int xorc = (rg << 3) | ((ks & 1) << 2);
    const float* __restrict__ hb = sm + OFF_H + rbase * 256 + ks * 64;
    const float* __restrict__ rb = sm + OFF_RH + rbase * 256 + ks * 64;

    for (int t = 0; t < tmax; ++t) {
        // ============ phase 1 GEMV: 4 gate cols x 4 rows x k-quarter ========
        ull acc[16];
#pragma unroll
        for (int x = 0; x < 16; ++x) acc[x] = 0ull;
#pragma unroll
        for (int i = 0; i < 16; ++i) {
            const float* wp = wgp + i * 512;
            ulonglong2 w0 = *(const ulonglong2*)(wp);
            ulonglong2 w1 = *(const ulonglong2*)(wp + 4);
            ulonglong2 w2 = *(const ulonglong2*)(wp + 8);
            ulonglong2 w3 = *(const ulonglong2*)(wp + 12);
            const float* hp = hb + ((i * 4) ^ xorc);
            ulonglong2 h0 = *(const ulonglong2*)(hp);
            ulonglong2 h1 = *(const ulonglong2*)(hp + 256);
            ulonglong2 h2 = *(const ulonglong2*)(hp + 512);
            ulonglong2 h3 = *(const ulonglong2*)(hp + 768);
            acc[0]  = fma2(w0.x, h0.x, acc[0]);   acc[0]  = fma2(w0.y, h0.y, acc[0]);
            acc[1]  = fma2(w0.x, h1.x, acc[1]);   acc[1]  = fma2(w0.y, h1.y, acc[1]);
            acc[2]  = fma2(w0.x, h2.x, acc[2]);   acc[2]  = fma2(w0.y, h2.y, acc[2]);
            acc[3]  = fma2(w0.x, h3.x, acc[3]);   acc[3]  = fma2(w0.y, h3.y, acc[3]);
            acc[4]  = fma2(w1.x, h0.x, acc[4]);   acc[4]  = fma2(w1.y, h0.y, acc[4]);
            acc[5]  = fma2(w1.x, h1.x, acc[5]);   acc[5]  = fma2(w1.y, h1.y, acc[5]);
            acc[6]  = fma2(w1.x, h2.x, acc[6]);   acc[6]  = fma2(w1.y, h2.y, acc[6]);
            acc[7]  = fma2(w1.x, h3.x, acc[7]);   acc[7]  = fma2(w1.y, h3.y, acc[7]);
            acc[8]  = fma2(w2.x, h0.x, acc[8]);   acc[8]  = fma2(w2.y, h0.y, acc[8]);
            acc[9]  = fma2(w2.x, h1.x, acc[9]);   acc[9]  = fma2(w2.y, h1.y, acc[9]);
            acc[10] = fma2(w2.x, h2.x, acc[10]);  acc[10] = fma2(w2.y, h2.y, acc[10]);
            acc[11] = fma2(w2.x, h3.x, acc[11]);  acc[11] = fma2(w2.y, h3.y, acc[11]);
            acc[12] = fma2(w3.x, h0.x, acc[12]);  acc[12] = fma2(w3.y, h0.y, acc[12]);
            acc[13] = fma2(w3.x, h1.x, acc[13]);  acc[13] = fma2(w3.y, h1.y, acc[13]);
            acc[14] = fma2(w3.x, h2.x, acc[14]);  acc[14] = fma2(w3.y, h2.y, acc[14]);
            acc[15] = fma2(w3.x, h3.x, acc[15]);  acc[15] = fma2(w3.y, h3.y, acc[15]);
        }
        float f[16];
#pragma unroll
        for (int x = 0; x < 16; ++x) { float2 v = unpack2(acc[x]); f[x] = v.x + v.y; }
#pragma unroll
        for (int x = 0; x < 16; ++x) f[x] += __shfl_xor_sync(0xffffffffu, f[x], 4);
#pragma unroll
        for (int x = 0; x < 16; ++x) f[x] += __shfl_xor_sync(0xffffffffu, f[x], 8);

        // gates + r*h publish (ks==0 lanes only; loads deferred past GEMV to
        // keep GEMV register pressure low)
        float g[16];
        if (ks0) {
#pragma unroll
            for (int rr = 0; rr < 4; ++rr) {
                float4 G = *(const float4*)(g_Gx +
                    ((size_t)(b0 + rbase + rr) * T_ + t) * 512 + gcolb);
                g[0 + rr]  = sigmoid_f(f[0 + rr]  + G.x);
                g[4 + rr]  = sigmoid_f(f[4 + rr]  + G.y);
                g[8 + rr]  = sigmoid_f(f[8 + rr]  + G.z);
                g[12 + rr] = sigmoid_f(f[12 + rr] + G.w);
            }
            if (isR) {
#pragma unroll
                for (int rr = 0; rr < 4; ++rr) {
                    int hx = hswz(rbase + rr, ccolb);
                    float4 ho = *(const float4*)(sm + OFF_H + hx);
                    ull lo = pack2(g[0 + rr] * ho.x, g[4 + rr]  * ho.y);
                    ull hi = pack2(g[8 + rr] * ho.z, g[12 + rr] * ho.w);
                    uint32_t la = smaddr + (uint32_t)(OFF_RH + hx) * 4;
#pragma unroll
                    for (uint32_t rk = 0; rk < CSZ; ++rk) {
                        uint32_t ra = mapa_sh(la, rk);
                        st_cluster_b64(ra, lo);
                        st_cluster_b64(ra + 8, hi);
                    }
                }
            }
        }
        CLUSTER_SYNC();   // A: RH complete everywhere; all H reads done

        // ============ phase 2 (u-warps): cand GEMV over RH; blend ===========
        if (!isR) {
            ull a2[16];
#pragma unroll
            for (int x = 0; x < 16; ++x) a2[x] = 0ull;
#pragma unroll
            for (int i = 0; i < 16; ++i) {
                const float* wp = wcp + i * 256;
                ulonglong2 w0 = *(const ulonglong2*)(wp);
                ulonglong2 w1 = *(const ulonglong2*)(wp + 4);
                ulonglong2 w2 = *(const ulonglong2*)(wp + 8);
                ulonglong2 w3 = *(const ulonglong2*)(wp + 12);
                const float* hp = rb + ((i * 4) ^ xorc);
                ulonglong2 h0 = *(const ulonglong2*)(hp);
                ulonglong2 h1 = *(const ulonglong2*)(hp + 256);
                ulonglong2 h2 = *(const ulonglong2*)(hp + 512);
                ulonglong2 h3 = *(const ulonglong2*)(hp + 768);
                a2[0]  = fma2(w0.x, h0.x, a2[0]);   a2[0]  = fma2(w0.y, h0.y, a2[0]);
                a2[1]  = fma2(w0.x, h1.x, a2[1]);   a2[1]  = fma2(w0.y, h1.y, a2[1]);
                a2[2]  = fma2(w0.x, h2.x, a2[2]);   a2[2]  = fma2(w0.y, h2.y, a2[2]);
                a2[3]  = fma2(w0.x, h3.x, a2[3]);   a2[3]  = fma2(w0.y, h3.y, a2[3]);
                a2[4]  = fma2(w1.x, h0.x, a2[4]);   a2[4]  = fma2(w1.y, h0.y, a2[4]);
                a2[5]  = fma2(w1.x, h1.x, a2[5]);   a2[5]  = fma2(w1.y, h1.y, a2[5]);
                a2[6]  = fma2(w1.x, h2.x, a2[6]);   a2[6]  = fma2(w1.y, h2.y, a2[6]);
                a2[7]  = fma2(w1.x, h3.x, a2[7]);   a2[7]  = fma2(w1.y, h3.y, a2[7]);
                a2[8]  = fma2(w2.x, h0.x, a2[8]);   a2[8]  = fma2(w2.y, h0.y, a2[8]);
                a2[9]  = fma2(w2.x, h1.x, a2[9]);   a2[9]  = fma2(w2.y, h1.y, a2[9]);
                a2[10] = fma2(w2.x, h2.x, a2[10]);  a2[10] = fma2(w2.y, h2.y, a2[10]);
                a2[11] = fma2(w2.x, h3.x, a2[11]);  a2[11] = fma2(w2.y, h3.y, a2[11]);
                a2[12] = fma2(w3.x, h0.x, a2[12]);  a2[12] = fma2(w3.y, h0.y, a2[12]);
                a2[13] = fma2(w3.x, h1.x, a2[13]);  a2[13] = fma2(w3.y, h1.y, a2[13]);
                a2[14] = fma2(w3.x, h2.x, a2[14]);  a2[14] = fma2(w3.y, h2.y, a2[14]);
                a2[15] = fma2(w3.x, h3.x, a2[15]);  a2[15] = fma2(w3.y, h3.y, a2[15]);
            }
            float f2[16];
#pragma unroll
            for (int x = 0; x < 16; ++x) { float2 v = unpack2(a2[x]); f2[x] = v.x + v.y; }
#pragma unroll
            for (int x = 0; x < 16; ++x) f2[x] += __shfl_xor_sync(0xffffffffu, f2[x], 4);
#pragma unroll
            for (int x = 0; x < 16; ++x) f2[x] += __shfl_xor_sync(0xffffffffu, f2[x], 8);

            if (ks0) {
#pragma unroll
                for (int rr = 0; rr < 4; ++rr) {
                    float4 X = *(const float4*)(g_Cx +
                        ((size_t)(b0 + rbase + rr) * T_ + t) * 256 + ccolb);
                    int hx = hswz(rbase + rr, ccolb);
                    float4 ho = *(const float4*)(sm + OFF_H + hx);  // old h
                    bool valid = (t < lenv[rr]);
                    float c0 = tanh_f(f2[0 + rr]  + X.x);
                    float c1 = tanh_f(f2[4 + rr]  + X.y);
                    float c2 = tanh_f(f2[8 + rr]  + X.z);
                    float c3 = tanh_f(f2[12 + rr] + X.w);
                    float n0 = g[0 + rr]  * ho.x + (1.f - g[0 + rr])  * c0;
                    float n1 = g[4 + rr]  * ho.y + (1.f - g[4 + rr])  * c1;
                    float n2 = g[8 + rr]  * ho.z + (1.f - g[8 + rr])  * c2;
                    float n3 = g[12 + rr] * ho.w + (1.f - g[12 + rr]) * c3;
                    float4 ov = valid ? make_float4(n0, n1, n2, n3)
                                      : make_float4(0.f, 0.f, 0.f, 0.f);
                    *(float4*)(out + ((size_t)(b0 + rbase + rr) * T_ + t) * 256
                               + ccolb) = ov;
                    ull lo = valid ? pack2(n0, n1) : pack2(ho.x, ho.y);
                    ull hi = valid ? pack2(n2, n3) : pack2(ho.z, ho.w);
                    uint32_t la = smaddr + (uint32_t)(OFF_H + hx) * 4;
#pragma unroll
                    for (uint32_t rk = 0; rk < CSZ; ++rk) {
                        uint32_t ra = mapa_sh(la, rk);
                        st_cluster_b64(ra, lo);
                        st_cluster_b64(ra + 8, hi);
                    }
                }
            }
        }
        CLUSTER_SYNC();   // B: new h complete everywhere; RH reads done
    }

    // zero-fill tail t in [tmax, 200): CTA c covers rows [c*4, c*4+4)
    for (int t = tmax; t < T_; ++t) {
#pragma unroll
        for (int q = 0; q < 2; ++q) {
            int cell = q * 512 + tid;            // 0..1023
            int row  = (int)c * 4 + (cell >> 8);
            int col  = cell & 255;
            out[((size_t)(b0 + row) * T_ + t) * 256 + col] = 0.f;
        }
    }
}

// ---------------------------------------------------------------------------
extern "C" void kernel_launch(void* const* d_in, const int* in_sizes, int n_in,
                              void* d_out, int out_size)
{
    const float* X  = (const float*)d_in[0];   // [512, 200, 256]
    const int*   L  = (const int*)  d_in[1];   // [512, 1]
    const float* Wg = (const float*)d_in[2];   // [512, 512]
    const float* bg = (const float*)d_in[3];   // [512]
    const float* Wc = (const float*)d_in[4];   // [512, 256]
    const float* bc = (const float*)d_in[5];   // [256]
    float* out = (float*)d_out;                // [512, 200, 256]

    // Input projections (parallel, independent of recurrence)
    gemm_precompute<<<dim3(BT_ / GBM, (2 * H_) / GBN), 256>>>(X, Wg, bg, L, 2 * H_);
    gemm_precompute<<<dim3(BT_ / GBM, H_ / GBN),       256>>>(X, Wc, bc, L, H_);

    // Sequential scan: 32 clusters x 4 CTAs, SMEM-resident weights
    cudaFuncSetAttribute(gru_recurrent,
                         cudaFuncAttributeMaxDynamicSharedMemorySize, SMEM_BYTES);
    gru_recurrent<<<NG_ * CSZ, THREADS_R, SMEM_BYTES>>>(Wg, Wc, L, out);
}

// round 16
// speedup vs baseline: 1.0747x; 1.0324x over previous
#include <cuda_runtime.h>
#include <math.h>
#include <stdint.h>

// Problem constants
#define B_   512
#define T_   200
#define D_   256
#define H_   256
#define BT_  (B_ * T_)      // 102400

// Recurrent-kernel geometry
#define RG_  16             // batch rows per cluster
#define NG_  (B_ / RG_)     // 32 clusters
#define CSZ  4              // CTAs per cluster (column split)
#define THREADS_R 512

typedef unsigned long long ull;

// Scratch (device globals; no allocation anywhere)
__device__ float g_Gx[BT_ * 2 * H_];   // [B*T, 512]  x@Wgx + gate_bias
__device__ float g_Cx[BT_ * H_];       // [B*T, 256]  x@Wcx + cand_bias

// SMEM layout (float offsets). Weight k-quarter regions padded +4 floats:
// per w-LDS the 8 (cp,ks) lanes hit chunks 4*cp + ks -> distinct (verified).
#define OFF_WG 0
#define WG_REG 8196        // 16 kb * 512 + 4
#define OFF_WC 32784       // 4 * WG_REG
#define WC_REG 4100        // 16 kb * 256 + 4
#define OFF_H  49184
#define OFF_RH 53280       // OFF_H + 4096
#define SMEM_FLOATS 57376
#define SMEM_BYTES (SMEM_FLOATS * 4)   // 229504 B (<= 232448 max)

// h storage swizzle (FIXED): XOR the in-row float index by
//   ((row>>2)&3)<<3   (rg -> chunk bits 1..2)
//   ((k>>7)&1)<<2     (k-quarter high bit -> chunk bit 0)   [was k>>6: BUG]
// plus k bit6 (ks&1) lands on chunk bit 4 via the address itself.
// Per h-LDS instruction the 16 (rg,ks) lanes now hit 16 distinct 16B bank
// quartets -> conflict-free. XOR bits >= 2, so float4 chunks stay contiguous.
__device__ __forceinline__ int hswz(int row, int k) {
    return row * 256 + (k ^ (((row >> 2) & 3) << 3) ^ (((k >> 7) & 1) << 2));
}

// ---- Blackwell packed fp32x2 helpers ----
__device__ __forceinline__ ull fma2(ull a, ull b, ull c) {
    ull d; asm("fma.rn.f32x2 %0, %1, %2, %3;" : "=l"(d) : "l"(a), "l"(b), "l"(c));
    return d;
}
__device__ __forceinline__ ull pack2(float lo, float hi) {
    ull d; asm("mov.b64 %0, {%1, %2};" : "=l"(d) : "f"(lo), "f"(hi));
    return d;
}
__device__ __forceinline__ float2 unpack2(ull v) {
    float2 r; asm("mov.b64 {%0, %1}, %2;" : "=f"(r.x), "=f"(r.y) : "l"(v));
    return r;
}
__device__ __forceinline__ float sigmoid_f(float x) { return 1.f / (1.f + __expf(-x)); }
__device__ __forceinline__ float tanh_f(float x)    { return 2.f / (1.f + __expf(-2.f * x)) - 1.f; }

__device__ __forceinline__ uint32_t smem_u32(const void* p) {
    uint32_t a;
    asm("{ .reg .u64 t; cvta.to.shared.u64 t, %1; cvt.u32.u64 %0, t; }" : "=r"(a) : "l"(p));
    return a;
}
__device__ __forceinline__ uint32_t ctarank() {
    uint32_t r; asm("mov.u32 %0, %%cluster_ctarank;" : "=r"(r));
    return r;
}
__device__ __forceinline__ uint32_t mapa_sh(uint32_t addr, uint32_t rank) {
    uint32_t r; asm("mapa.shared::cluster.u32 %0, %1, %2;" : "=r"(r) : "r"(addr), "r"(rank));
    return r;
}
__device__ __forceinline__ void st_cluster_b64(uint32_t addr, ull v) {
    asm volatile("st.shared::cluster.b64 [%0], %1;" :: "r"(addr), "l"(v) : "memory");
}
#define CLUSTER_SYNC() do { \
    asm volatile("barrier.cluster.arrive.aligned;" ::: "memory"); \
    asm volatile("barrier.cluster.wait.aligned;" ::: "memory");   \
} while (0)

// ---------------------------------------------------------------------------
// Precompute GEMM (unchanged)
// ---------------------------------------------------------------------------
#define GBM 128
#define GBN 64
#define GBK 16

__global__ __launch_bounds__(256) void gemm_precompute(
    const float* __restrict__ X,
    const float* __restrict__ W,
    const float* __restrict__ bias,
    const int*   __restrict__ seqlen,
    int N)
{
    const int r0 = blockIdx.x * GBM;
    const int n0 = blockIdx.y * GBN;

    {
        int b0 = r0 / T_;
        int b1 = (r0 + GBM - 1) / T_;
        bool needed = false;
        for (int b = b0; b <= b1; ++b) {
            int tstart = r0 - b * T_;
            if (tstart < 0) tstart = 0;
            if (tstart < seqlen[b]) { needed = true; break; }
        }
        if (!needed) return;
    }

    float* __restrict__ C = (N == 2 * H_) ? g_Gx : g_Cx;

    __shared__ float As[GBK][GBM];
    __shared__ float Bs[GBK][GBN];

    const int tid = threadIdx.x;
    const int am  = tid >> 2;
    const int ak  = (tid & 3) * 4;
    const int bk  = tid >> 4;
    const int bn  = (tid & 15) * 4;
    const int tm  = (tid >> 4) * 8;
    const int tn  = (tid & 15) * 4;

    ull acc2[4][4];
#pragma unroll
    for (int p = 0; p < 4; ++p)
#pragma unroll
        for (int j = 0; j < 4; ++j) acc2[p][j] = 0ull;

    for (int kt = 0; kt < D_; kt += GBK) {
        float4 a0 = *(const float4*)(X + (size_t)(r0 + am) * D_ + kt + ak);
        float4 a1 = *(const float4*)(X + (size_t)(r0 + am + 64) * D_ + kt + ak);
        As[ak + 0][am] = a0.x;  As[ak + 1][am] = a0.y;
        As[ak + 2][am] = a0.z;  As[ak + 3][am] = a0.w;
        As[ak + 0][am + 64] = a1.x;  As[ak + 1][am + 64] = a1.y;
        As[ak + 2][am + 64] = a1.z;  As[ak + 3][am + 64] = a1.w;
        *(float4*)&Bs[bk][bn] = *(const float4*)(W + (size_t)(kt + bk) * N + n0 + bn);
        __syncthreads();

#pragma unroll
        for (int k = 0; k < GBK; ++k) {
            ulonglong2 a01 = *(const ulonglong2*)&As[k][tm];
            ulonglong2 a23 = *(const ulonglong2*)&As[k][tm + 4];
            float4 bq = *(const float4*)&Bs[k][tn];
            ull ap[4] = { a01.x, a01.y, a23.x, a23.y };
            ull bp[4] = { pack2(bq.x, bq.x), pack2(bq.y, bq.y),
                          pack2(bq.z, bq.z), pack2(bq.w, bq.w) };
#pragma unroll
            for (int p = 0; p < 4; ++p)
#pragma unroll
                for (int j = 0; j < 4; ++j)
                    acc2[p][j] = fma2(ap[p], bp[j], acc2[p][j]);
        }
        __syncthreads();
    }

    float4 bv = *(const float4*)(bias + n0 + tn);
#pragma unroll
    for (int p = 0; p < 4; ++p) {
        float2 c0 = unpack2(acc2[p][0]);
        float2 c1 = unpack2(acc2[p][1]);
        float2 c2 = unpack2(acc2[p][2]);
        float2 c3 = unpack2(acc2[p][3]);
        int row0 = r0 + tm + 2 * p;
        float4 o0 = make_float4(c0.x + bv.x, c1.x + bv.y, c2.x + bv.z, c3.x + bv.w);
        float4 o1 = make_float4(c0.y + bv.x, c1.y + bv.y, c2.y + bv.z, c3.y + bv.w);
        *(float4*)(C + (size_t)row0 * N + n0 + tn) = o0;
        *(float4*)(C + (size_t)(row0 + 1) * N + n0 + tn) = o1;
    }
}

// ---------------------------------------------------------------------------
// Recurrent kernel: R15 structure with (1) conflict-free h swizzle and
// (2) Gx/Cx prefetched where GEMV latency hides them.
// ---------------------------------------------------------------------------
__global__ __launch_bounds__(THREADS_R, 1) __cluster_dims__(CSZ, 1, 1)
void gru_recurrent(const float* __restrict__ Wg,   // [512, 512]
                   const float* __restrict__ Wc,   // [512, 256]
                   const int*   __restrict__ seqlen,
                   float* __restrict__ out)        // [B, T, 256]
{
    extern __shared__ float sm[];
    const int tid  = threadIdx.x;
    const int lane = tid & 31;
    const int w    = tid >> 5;
    const uint32_t c = ctarank();
    const int b0 = (blockIdx.x / CSZ) * RG_;

    const int rg = lane & 3;
    const int ks = (lane >> 2) & 3;
    const int cp = lane >> 4;
    const int rbase = rg * 4;
    const bool isR = (w < 8);
    const int jquad = w * 8 + cp * 4;                 // [0,128)
    const int jc    = isR ? jquad : (jquad - 64);     // [0,64)
    const int gcolb = isR ? ((int)c * 64 + jquad) : (256 + (int)c * 64 + jc);
    const int ccolb = (int)c * 64 + jc;
    const bool ks0  = (ks == 0);

    // ---- load weight slices into SMEM (k-quarter regions, padded) ----
    for (int idx = tid; idx < 64 * 128; idx += THREADS_R) {
        int kb = idx >> 7, jj = idx & 127;
        int col = (jj < 64) ? ((int)c * 64 + jj) : (256 + (int)c * 64 + (jj - 64));
        float* dst = sm + OFF_WG + (kb >> 4) * WG_REG + (kb & 15) * 512 + jj * 4;
#pragma unroll
        for (int i = 0; i < 4; ++i)
            dst[i] = Wg[(256 + kb * 4 + i) * 512 + col];
    }
    for (int idx = tid; idx < 64 * 64; idx += THREADS_R) {
        int kb = idx >> 6, jj = idx & 63;
        int col = (int)c * 64 + jj;
        float* dst = sm + OFF_WC + (kb >> 4) * WC_REG + (kb & 15) * 256 + jj * 4;
#pragma unroll
        for (int i = 0; i < 4; ++i)
            dst[i] = Wc[(256 + kb * 4 + i) * 256 + col];
    }
    for (int i = tid; i < 16 * 256; i += THREADS_R) sm[OFF_H + i] = 0.f;

    int tmax = 0;
    for (int rr = 0; rr < RG_; ++rr) tmax = max(tmax, seqlen[b0 + rr]);
    int lenv[4];
#pragma unroll
    for (int rr = 0; rr < 4; ++rr) lenv[rr] = seqlen[b0 + rbase + rr];

    __syncthreads();
    CLUSTER_SYNC();

    const uint32_t smaddr = smem_u32(sm);
    const float* __restrict__ wgp = sm + OFF_WG + ks * WG_REG + jquad * 4;
    const float* __restrict__ wcp = sm + OFF_WC + ks * WC_REG + jc * 4;
    // FIXED reader xor: ks high bit -> chunk bit0 (matches hswz's k>>7 term)
    const int xorc = (rg << 3) | ((ks >> 1) << 2);
    const float* __restrict__ hb = sm + OFF_H + rbase * 256 + ks * 64;
    const float* __restrict__ rb = sm + OFF_RH + rbase * 256 + ks * 64;

    for (int t = 0; t < tmax; ++t) {
        // ---- prefetch Gx at step top: DRAM/L2 latency hides under GEMV1 ----
        float4 Gpre[4];
        if (ks0) {
#pragma unroll
            for (int rr = 0; rr < 4; ++rr)
                Gpre[rr] = *(const float4*)(g_Gx +
                    ((size_t)(b0 + rbase + rr) * T_ + t) * 512 + gcolb);
        }

        // ============ phase 1 GEMV: 4 gate cols x 4 rows x k-quarter ========
        ull acc[16];
#pragma unroll
        for (int x = 0; x < 16; ++x) acc[x] = 0ull;
#pragma unroll
        for (int i = 0; i < 16; ++i) {
            const float* wp = wgp + i * 512;
            ulonglong2 w0 = *(const ulonglong2*)(wp);
            ulonglong2 w1 = *(const ulonglong2*)(wp + 4);
            ulonglong2 w2 = *(const ulonglong2*)(wp + 8);
            ulonglong2 w3 = *(const ulonglong2*)(wp + 12);
            const float* hp = hb + ((i * 4) ^ xorc);
            ulonglong2 h0 = *(const ulonglong2*)(hp);
            ulonglong2 h1 = *(const ulonglong2*)(hp + 256);
            ulonglong2 h2 = *(const ulonglong2*)(hp + 512);
            ulonglong2 h3 = *(const ulonglong2*)(hp + 768);
            acc[0]  = fma2(w0.x, h0.x, acc[0]);   acc[0]  = fma2(w0.y, h0.y, acc[0]);
            acc[1]  = fma2(w0.x, h1.x, acc[1]);   acc[1]  = fma2(w0.y, h1.y, acc[1]);
            acc[2]  = fma2(w0.x, h2.x, acc[2]);   acc[2]  = fma2(w0.y, h2.y, acc[2]);
            acc[3]  = fma2(w0.x, h3.x, acc[3]);   acc[3]  = fma2(w0.y, h3.y, acc[3]);
            acc[4]  = fma2(w1.x, h0.x, acc[4]);   acc[4]  = fma2(w1.y, h0.y, acc[4]);
            acc[5]  = fma2(w1.x, h1.x, acc[5]);   acc[5]  = fma2(w1.y, h1.y, acc[5]);
            acc[6]  = fma2(w1.x, h2.x, acc[6]);   acc[6]  = fma2(w1.y, h2.y, acc[6]);
            acc[7]  = fma2(w1.x, h3.x, acc[7]);   acc[7]  = fma2(w1.y, h3.y, acc[7]);
            acc[8]  = fma2(w2.x, h0.x, acc[8]);   acc[8]  = fma2(w2.y, h0.y, acc[8]);
            acc[9]  = fma2(w2.x, h1.x, acc[9]);   acc[9]  = fma2(w2.y, h1.y, acc[9]);
            acc[10] = fma2(w2.x, h2.x, acc[10]);  acc[10] = fma2(w2.y, h2.y, acc[10]);
            acc[11] = fma2(w2.x, h3.x, acc[11]);  acc[11] = fma2(w2.y, h3.y, acc[11]);
            acc[12] = fma2(w3.x, h0.x, acc[12]);  acc[12] = fma2(w3.y, h0.y, acc[12]);
            acc[13] = fma2(w3.x, h1.x, acc[13]);  acc[13] = fma2(w3.y, h1.y, acc[13]);
            acc[14] = fma2(w3.x, h2.x, acc[14]);  acc[14] = fma2(w3.y, h2.y, acc[14]);
            acc[15] = fma2(w3.x, h3.x, acc[15]);  acc[15] = fma2(w3.y, h3.y, acc[15]);
        }
        float f[16];
#pragma unroll
        for (int x = 0; x < 16; ++x) { float2 v = unpack2(acc[x]); f[x] = v.x + v.y; }
#pragma unroll
        for (int x = 0; x < 16; ++x) f[x] += __shfl_xor_sync(0xffffffffu, f[x], 4);
#pragma unroll
        for (int x = 0; x < 16; ++x) f[x] += __shfl_xor_sync(0xffffffffu, f[x], 8);

        // gates + r*h publish (ks==0 lanes only; Gx already in registers)
        float g[16];
        if (ks0) {
#pragma unroll
            for (int rr = 0; rr < 4; ++rr) {
                g[0 + rr]  = sigmoid_f(f[0 + rr]  + Gpre[rr].x);
                g[4 + rr]  = sigmoid_f(f[4 + rr]  + Gpre[rr].y);
                g[8 + rr]  = sigmoid_f(f[8 + rr]  + Gpre[rr].z);
                g[12 + rr] = sigmoid_f(f[12 + rr] + Gpre[rr].w);
            }
            if (isR) {
#pragma unroll
                for (int rr = 0; rr < 4; ++rr) {
                    int hx = hswz(rbase + rr, ccolb);
                    float4 ho = *(const float4*)(sm + OFF_H + hx);
                    ull lo = pack2(g[0 + rr] * ho.x, g[4 + rr]  * ho.y);
                    ull hi = pack2(g[8 + rr] * ho.z, g[12 + rr] * ho.w);
                    uint32_t la = smaddr + (uint32_t)(OFF_RH + hx) * 4;
#pragma unroll
                    for (uint32_t rk = 0; rk < CSZ; ++rk) {
                        uint32_t ra = mapa_sh(la, rk);
                        st_cluster_b64(ra, lo);
                        st_cluster_b64(ra + 8, hi);
                    }
                }
            }
        }
        CLUSTER_SYNC();   // A: RH complete everywhere; all H reads done

        // ============ phase 2 (u-warps): cand GEMV over RH; blend ===========
        if (!isR) {
            // prefetch Cx now: latency hides under GEMV2
            float4 Xpre[4];
            if (ks0) {
#pragma unroll
                for (int rr = 0; rr < 4; ++rr)
                    Xpre[rr] = *(const float4*)(g_Cx +
                        ((size_t)(b0 + rbase + rr) * T_ + t) * 256 + ccolb);
            }
            ull a2[16];
#pragma unroll
            for (int x = 0; x < 16; ++x) a2[x] = 0ull;
#pragma unroll
            for (int i = 0; i < 16; ++i) {
                const float* wp = wcp + i * 256;
                ulonglong2 w0 = *(const ulonglong2*)(wp);
                ulonglong2 w1 = *(const ulonglong2*)(wp + 4);
                ulonglong2 w2 = *(const ulonglong2*)(wp + 8);
                ulonglong2 w3 = *(const ulonglong2*)(wp + 12);
                const float* hp = rb + ((i * 4) ^ xorc);
                ulonglong2 h0 = *(const ulonglong2*)(hp);
                ulonglong2 h1 = *(const ulonglong2*)(hp + 256);
                ulonglong2 h2 = *(const ulonglong2*)(hp + 512);
                ulonglong2 h3 = *(const ulonglong2*)(hp + 768);
                a2[0]  = fma2(w0.x, h0.x, a2[0]);   a2[0]  = fma2(w0.y, h0.y, a2[0]);
                a2[1]  = fma2(w0.x, h1.x, a2[1]);   a2[1]  = fma2(w0.y, h1.y, a2[1]);
                a2[2]  = fma2(w0.x, h2.x, a2[2]);   a2[2]  = fma2(w0.y, h2.y, a2[2]);
                a2[3]  = fma2(w0.x, h3.x, a2[3]);   a2[3]  = fma2(w0.y, h3.y, a2[3]);
                a2[4]  = fma2(w1.x, h0.x, a2[4]);   a2[4]  = fma2(w1.y, h0.y, a2[4]);
                a2[5]  = fma2(w1.x, h1.x, a2[5]);   a2[5]  = fma2(w1.y, h1.y, a2[5]);
                a2[6]  = fma2(w1.x, h2.x, a2[6]);   a2[6]  = fma2(w1.y, h2.y, a2[6]);
                a2[7]  = fma2(w1.x, h3.x, a2[7]);   a2[7]  = fma2(w1.y, h3.y, a2[7]);
                a2[8]  = fma2(w2.x, h0.x, a2[8]);   a2[8]  = fma2(w2.y, h0.y, a2[8]);
                a2[9]  = fma2(w2.x, h1.x, a2[9]);   a2[9]  = fma2(w2.y, h1.y, a2[9]);
                a2[10] = fma2(w2.x, h2.x, a2[10]);  a2[10] = fma2(w2.y, h2.y, a2[10]);
                a2[11] = fma2(w2.x, h3.x, a2[11]);  a2[11] = fma2(w2.y, h3.y, a2[11]);
                a2[12] = fma2(w3.x, h0.x, a2[12]);  a2[12] = fma2(w3.y, h0.y, a2[12]);
                a2[13] = fma2(w3.x, h1.x, a2[13]);  a2[13] = fma2(w3.y, h1.y, a2[13]);
                a2[14] = fma2(w3.x, h2.x, a2[14]);  a2[14] = fma2(w3.y, h2.y, a2[14]);
                a2[15] = fma2(w3.x, h3.x, a2[15]);  a2[15] = fma2(w3.y, h3.y, a2[15]);
            }
            float f2[16];
#pragma unroll
            for (int x = 0; x < 16; ++x) { float2 v = unpack2(a2[x]); f2[x] = v.x + v.y; }
#pragma unroll
            for (int x = 0; x < 16; ++x) f2[x] += __shfl_xor_sync(0xffffffffu, f2[x], 4);
#pragma unroll
            for (int x = 0; x < 16; ++x) f2[x] += __shfl_xor_sync(0xffffffffu, f2[x], 8);

            if (ks0) {
#pragma unroll
                for (int rr = 0; rr < 4; ++rr) {
                    int hx = hswz(rbase + rr, ccolb);
                    float4 ho = *(const float4*)(sm + OFF_H + hx);  // old h
                    bool valid = (t < lenv[rr]);
                    float c0 = tanh_f(f2[0 + rr]  + Xpre[rr].x);
                    float c1 = tanh_f(f2[4 + rr]  + Xpre[rr].y);
                    float c2 = tanh_f(f2[8 + rr]  + Xpre[rr].z);
                    float c3 = tanh_f(f2[12 + rr] + Xpre[rr].w);
                    float n0 = g[0 + rr]  * ho.x + (1.f - g[0 + rr])  * c0;
                    float n1 = g[4 + rr]  * ho.y + (1.f - g[4 + rr])  * c1;
                    float n2 = g[8 + rr]  * ho.z + (1.f - g[8 + rr])  * c2;
                    float n3 = g[12 + rr] * ho.w + (1.f - g[12 + rr]) * c3;
                    float4 ov = valid ? make_float4(n0, n1, n2, n3)
                                      : make_float4(0.f, 0.f, 0.f, 0.f);
                    *(float4*)(out + ((size_t)(b0 + rbase + rr) * T_ + t) * 256
                               + ccolb) = ov;
                    ull lo = valid ? pack2(n0, n1) : pack2(ho.x, ho.y);
                    ull hi = valid ? pack2(n2, n3) : pack2(ho.z, ho.w);
                    uint32_t la = smaddr + (uint32_t)(OFF_H + hx) * 4;
#pragma unroll
                    for (uint32_t rk = 0; rk < CSZ; ++rk) {
                        uint32_t ra = mapa_sh(la, rk);
                        st_cluster_b64(ra, lo);
                        st_cluster_b64(ra + 8, hi);
                    }
                }
            }
        }
        CLUSTER_SYNC();   // B: new h complete everywhere; RH reads done
    }

    // zero-fill tail t in [tmax, 200): CTA c covers rows [c*4, c*4+4)
    for (int t = tmax; t < T_; ++t) {
#pragma unroll
        for (int q = 0; q < 2; ++q) {
            int cell = q * 512 + tid;            // 0..1023
            int row  = (int)c * 4 + (cell >> 8);
            int col  = cell & 255;
            out[((size_t)(b0 + row) * T_ + t) * 256 + col] = 0.f;
        }
    }
}

// ---------------------------------------------------------------------------
extern "C" void kernel_launch(void* const* d_in, const int* in_sizes, int n_in,
                              void* d_out, int out_size)
{
    const float* X  = (const float*)d_in[0];   // [512, 200, 256]
    const int*   L  = (const int*)  d_in[1];   // [512, 1]
    const float* Wg = (const float*)d_in[2];   // [512, 512]
    const float* bg = (const float*)d_in[3];   // [512]
    const float* Wc = (const float*)d_in[4];   // [512, 256]
    const float* bc = (const float*)d_in[5];   // [256]
    float* out = (float*)d_out;                // [512, 200, 256]

    // Input projections (parallel, independent of recurrence)
    gemm_precompute<<<dim3(BT_ / GBM, (2 * H_) / GBN), 256>>>(X, Wg, bg, L, 2 * H_);
    gemm_precompute<<<dim3(BT_ / GBM, H_ / GBN),       256>>>(X, Wc, bc, L, H_);

    // Sequential scan: 32 clusters x 4 CTAs, SMEM-resident weights
    cudaFuncSetAttribute(gru_recurrent,
                         cudaFuncAttributeMaxDynamicSharedMemorySize, SMEM_BYTES);
    gru_recurrent<<<NG_ * CSZ, THREADS_R, SMEM_BYTES>>>(Wg, Wc, L, out);
}

// round 17
// speedup vs baseline: 1.1015x; 1.0249x over previous
#include <cuda_runtime.h>
#include <math.h>
#include <stdint.h>

// Problem constants
#define B_   512
#define T_   200
#define D_   256
#define H_   256
#define BT_  (B_ * T_)      // 102400

// Recurrent-kernel geometry
#define RG_  16             // batch rows per cluster
#define NG_  (B_ / RG_)     // 32 clusters
#define CSZ  4              // CTAs per cluster (column split)
#define THREADS_R 512

typedef unsigned long long ull;

// Scratch (device globals; no allocation anywhere)
__device__ float g_Gx[BT_ * 2 * H_];   // [B*T, 512]  x@Wgx + gate_bias
__device__ float g_Cx[BT_ * H_];       // [B*T, 256]  x@Wcx + cand_bias

// SMEM layout (float offsets). Weight k-quarter regions padded +4 floats:
// per w-LDS the 8 (cp,ks) lanes hit chunks 4*cp + ks -> distinct.
#define OFF_WG 0
#define WG_REG 8196        // 16 kb * 512 + 4
#define OFF_WC 32784       // 4 * WG_REG
#define WC_REG 4100        // 16 kb * 256 + 4
#define OFF_H  49184
#define OFF_RH 53280       // OFF_H + 4096
#define SMEM_FLOATS 57376
#define SMEM_BYTES (SMEM_FLOATS * 4)   // 229504 B (<= 232448 max)

// h storage swizzle: 16 distinct addresses per h-LDS -> 2-wavefront floor,
// achieved by spreading (rg, ks>>1) across chunk space.
__device__ __forceinline__ int hswz(int row, int k) {
    return row * 256 + (k ^ (((row >> 2) & 3) << 3) ^ (((k >> 7) & 1) << 2));
}

// ---- Blackwell packed fp32x2 helpers ----
__device__ __forceinline__ ull fma2(ull a, ull b, ull c) {
    ull d; asm("fma.rn.f32x2 %0, %1, %2, %3;" : "=l"(d) : "l"(a), "l"(b), "l"(c));
    return d;
}
__device__ __forceinline__ ull pack2(float lo, float hi) {
    ull d; asm("mov.b64 %0, {%1, %2};" : "=l"(d) : "f"(lo), "f"(hi));
    return d;
}
__device__ __forceinline__ float2 unpack2(ull v) {
    float2 r; asm("mov.b64 {%0, %1}, %2;" : "=f"(r.x), "=f"(r.y) : "l"(v));
    return r;
}
__device__ __forceinline__ float sigmoid_f(float x) { return 1.f / (1.f + __expf(-x)); }
__device__ __forceinline__ float tanh_f(float x)    { return 2.f / (1.f + __expf(-2.f * x)) - 1.f; }

__device__ __forceinline__ uint32_t smem_u32(const void* p) {
    uint32_t a;
    asm("{ .reg .u64 t; cvta.to.shared.u64 t, %1; cvt.u32.u64 %0, t; }" : "=r"(a) : "l"(p));
    return a;
}
__device__ __forceinline__ uint32_t ctarank() {
    uint32_t r; asm("mov.u32 %0, %%cluster_ctarank;" : "=r"(r));
    return r;
}
__device__ __forceinline__ uint32_t mapa_sh(uint32_t addr, uint32_t rank) {
    uint32_t r; asm("mapa.shared::cluster.u32 %0, %1, %2;" : "=r"(r) : "r"(addr), "r"(rank));
    return r;
}
__device__ __forceinline__ void st_cluster_b64(uint32_t addr, ull v) {
    asm volatile("st.shared::cluster.b64 [%0], %1;" :: "r"(addr), "l"(v) : "memory");
}
#define CLUSTER_SYNC() do { \
    asm volatile("barrier.cluster.arrive.aligned;" ::: "memory"); \
    asm volatile("barrier.cluster.wait.aligned;" ::: "memory");   \
} while (0)

// ---------------------------------------------------------------------------
// Precompute GEMM: C[M=102400, N] = X[M,256] @ W[256,N] + bias[N]
// REWORKED (measured L1-bound at 82.8%):
//  - 8x8 register tile (GBN=128): LDS bytes per fma2 3B -> 2B; X re-reads halve
//  - Bs column swizzle: inner b-LDS conflict degree 4 -> 2 (floor)
// ---------------------------------------------------------------------------
#define GBM 128
#define GBN 128
#define GBK 16

__device__ __forceinline__ int bswz(int j) {        // 8-col-aligned safe
    return j ^ (((j >> 5) & 3) << 2);
}

__global__ __launch_bounds__(256) void gemm_precompute(
    const float* __restrict__ X,
    const float* __restrict__ W,
    const float* __restrict__ bias,
    const int*   __restrict__ seqlen,
    int N)
{
    const int r0 = blockIdx.x * GBM;
    const int n0 = blockIdx.y * GBN;

    {   // skip tiles fully past sequence_length
        int b0 = r0 / T_;
        int b1 = (r0 + GBM - 1) / T_;
        bool needed = false;
        for (int b = b0; b <= b1; ++b) {
            int tstart = r0 - b * T_;
            if (tstart < 0) tstart = 0;
            if (tstart < seqlen[b]) { needed = true; break; }
        }
        if (!needed) return;
    }

    float* __restrict__ C = (N == 2 * H_) ? g_Gx : g_Cx;

    __shared__ float As[GBK][GBM];
    __shared__ float Bs[GBK][GBN];

    const int tid = threadIdx.x;
    const int am  = tid >> 2;               // 0..63
    const int ak  = (tid & 3) * 4;          // 0,4,8,12
    const int bk  = tid >> 4;               // 0..15
    const int bn  = (tid & 15) * 8;         // 0..120
    const int tm  = (tid >> 4) * 8;         // 0..120
    const int tn  = (tid & 15) * 8;         // 0..120
    const int tns = bswz(tn);

    ull acc[4][8];
#pragma unroll
    for (int p = 0; p < 4; ++p)
#pragma unroll
        for (int j = 0; j < 8; ++j) acc[p][j] = 0ull;

    for (int kt = 0; kt < D_; kt += GBK) {
        float4 a0 = *(const float4*)(X + (size_t)(r0 + am) * D_ + kt + ak);
        float4 a1 = *(const float4*)(X + (size_t)(r0 + am + 64) * D_ + kt + ak);
        As[ak + 0][am] = a0.x;  As[ak + 1][am] = a0.y;
        As[ak + 2][am] = a0.z;  As[ak + 3][am] = a0.w;
        As[ak + 0][am + 64] = a1.x;  As[ak + 1][am + 64] = a1.y;
        As[ak + 2][am + 64] = a1.z;  As[ak + 3][am + 64] = a1.w;
        {
            float4 b0 = *(const float4*)(W + (size_t)(kt + bk) * N + n0 + bn);
            float4 b1 = *(const float4*)(W + (size_t)(kt + bk) * N + n0 + bn + 4);
            int bns = bswz(bn);
            *(float4*)&Bs[bk][bns]     = b0;
            *(float4*)&Bs[bk][bns ^ 4] = b1;
        }
        __syncthreads();

#pragma unroll
        for (int k = 0; k < GBK; ++k) {
            ulonglong2 a01 = *(const ulonglong2*)&As[k][tm];
            ulonglong2 a23 = *(const ulonglong2*)&As[k][tm + 4];
            float4 bqa = *(const float4*)&Bs[k][tns];
            float4 bqb = *(const float4*)&Bs[k][tns ^ 4];
            ull ap[4] = { a01.x, a01.y, a23.x, a23.y };
            ull bp[8] = { pack2(bqa.x, bqa.x), pack2(bqa.y, bqa.y),
                          pack2(bqa.z, bqa.z), pack2(bqa.w, bqa.w),
                          pack2(bqb.x, bqb.x), pack2(bqb.y, bqb.y),
                          pack2(bqb.z, bqb.z), pack2(bqb.w, bqb.w) };
#pragma unroll
            for (int p = 0; p < 4; ++p)
#pragma unroll
                for (int j = 0; j < 8; ++j)
                    acc[p][j] = fma2(ap[p], bp[j], acc[p][j]);
        }
        __syncthreads();
    }

    float4 bv0 = *(const float4*)(bias + n0 + tn);
    float4 bv1 = *(const float4*)(bias + n0 + tn + 4);
#pragma unroll
    for (int p = 0; p < 4; ++p) {
        float2 cc[8];
#pragma unroll
        for (int j = 0; j < 8; ++j) cc[j] = unpack2(acc[p][j]);
        int row0 = r0 + tm + 2 * p;
        float4 o0a = make_float4(cc[0].x + bv0.x, cc[1].x + bv0.y,
                                 cc[2].x + bv0.z, cc[3].x + bv0.w);
        float4 o0b = make_float4(cc[4].x + bv1.x, cc[5].x + bv1.y,
                                 cc[6].x + bv1.z, cc[7].x + bv1.w);
        float4 o1a = make_float4(cc[0].y + bv0.x, cc[1].y + bv0.y,
                                 cc[2].y + bv0.z, cc[3].y + bv0.w);
        float4 o1b = make_float4(cc[4].y + bv1.x, cc[5].y + bv1.y,
                                 cc[6].y + bv1.z, cc[7].y + bv1.w);
        *(float4*)(C + (size_t)row0 * N + n0 + tn)           = o0a;
        *(float4*)(C + (size_t)row0 * N + n0 + tn + 4)       = o0b;
        *(float4*)(C + (size_t)(row0 + 1) * N + n0 + tn)     = o1a;
        *(float4*)(C + (size_t)(row0 + 1) * N + n0 + tn + 4) = o1b;
    }
}

// ---------------------------------------------------------------------------
// Recurrent kernel: UNCHANGED from round 16 (best known recurrent config).
// ---------------------------------------------------------------------------
__global__ __launch_bounds__(THREADS_R, 1) __cluster_dims__(CSZ, 1, 1)
void gru_recurrent(const float* __restrict__ Wg,   // [512, 512]
                   const float* __restrict__ Wc,   // [512, 256]
                   const int*   __restrict__ seqlen,
                   float* __restrict__ out)        // [B, T, 256]
{
    extern __shared__ float sm[];
    const int tid  = threadIdx.x;
    const int lane = tid & 31;
    const int w    = tid >> 5;
    const uint32_t c = ctarank();
    const int b0 = (blockIdx.x / CSZ) * RG_;

    const int rg = lane & 3;
    const int ks = (lane >> 2) & 3;
    const int cp = lane >> 4;
    const int rbase = rg * 4;
    const bool isR = (w < 8);
    const int jquad = w * 8 + cp * 4;                 // [0,128)
    const int jc    = isR ? jquad : (jquad - 64);     // [0,64)
    const int gcolb = isR ? ((int)c * 64 + jquad) : (256 + (int)c * 64 + jc);
    const int ccolb = (int)c * 64 + jc;
    const bool ks0  = (ks == 0);

    // ---- load weight slices into SMEM (k-quarter regions, padded) ----
    for (int idx = tid; idx < 64 * 128; idx += THREADS_R) {
        int kb = idx >> 7, jj = idx & 127;
        int col = (jj < 64) ? ((int)c * 64 + jj) : (256 + (int)c * 64 + (jj - 64));
        float* dst = sm + OFF_WG + (kb >> 4) * WG_REG + (kb & 15) * 512 + jj * 4;
#pragma unroll
        for (int i = 0; i < 4; ++i)
            dst[i] = Wg[(256 + kb * 4 + i) * 512 + col];
    }
    for (int idx = tid; idx < 64 * 64; idx += THREADS_R) {
        int kb = idx >> 6, jj = idx & 63;
        int col = (int)c * 64 + jj;
        float* dst = sm + OFF_WC + (kb >> 4) * WC_REG + (kb & 15) * 256 + jj * 4;
#pragma unroll
        for (int i = 0; i < 4; ++i)
            dst[i] = Wc[(256 + kb * 4 + i) * 256 + col];
    }
    for (int i = tid; i < 16 * 256; i += THREADS_R) sm[OFF_H + i] = 0.f;

    int tmax = 0;
    for (int rr = 0; rr < RG_; ++rr) tmax = max(tmax, seqlen[b0 + rr]);
    int lenv[4];
#pragma unroll
    for (int rr = 0; rr < 4; ++rr) lenv[rr] = seqlen[b0 + rbase + rr];

    __syncthreads();
    CLUSTER_SYNC();

    const uint32_t smaddr = smem_u32(sm);
    const float* __restrict__ wgp = sm + OFF_WG + ks * WG_REG + jquad * 4;
    const float* __restrict__ wcp = sm + OFF_WC + ks * WC_REG + jc * 4;
    const int xorc = (rg << 3) | ((ks >> 1) << 2);
    const float* __restrict__ hb = sm + OFF_H + rbase * 256 + ks * 64;
    const float* __restrict__ rb = sm + OFF_RH + rbase * 256 + ks * 64;

    for (int t = 0; t < tmax; ++t) {
        // ---- prefetch Gx at step top: latency hides under GEMV1 ----
        float4 Gpre[4];
        if (ks0) {
#pragma unroll
            for (int rr = 0; rr < 4; ++rr)
                Gpre[rr] = *(const float4*)(g_Gx +
                    ((size_t)(b0 + rbase + rr) * T_ + t) * 512 + gcolb);
        }

        // ============ phase 1 GEMV: 4 gate cols x 4 rows x k-quarter ========
        ull acc[16];
#pragma unroll
        for (int x = 0; x < 16; ++x) acc[x] = 0ull;
#pragma unroll
        for (int i = 0; i < 16; ++i) {
            const float* wp = wgp + i * 512;
            ulonglong2 w0 = *(const ulonglong2*)(wp);
            ulonglong2 w1 = *(const ulonglong2*)(wp + 4);
            ulonglong2 w2 = *(const ulonglong2*)(wp + 8);
            ulonglong2 w3 = *(const ulonglong2*)(wp + 12);
            const float* hp = hb + ((i * 4) ^ xorc);
            ulonglong2 h0 = *(const ulonglong2*)(hp);
            ulonglong2 h1 = *(const ulonglong2*)(hp + 256);
            ulonglong2 h2 = *(const ulonglong2*)(hp + 512);
            ulonglong2 h3 = *(const ulonglong2*)(hp + 768);
            acc[0]  = fma2(w0.x, h0.x, acc[0]);   acc[0]  = fma2(w0.y, h0.y, acc[0]);
            acc[1]  = fma2(w0.x, h1.x, acc[1]);   acc[1]  = fma2(w0.y, h1.y, acc[1]);
            acc[2]  = fma2(w0.x, h2.x, acc[2]);   acc[2]  = fma2(w0.y, h2.y, acc[2]);
            acc[3]  = fma2(w0.x, h3.x, acc[3]);   acc[3]  = fma2(w0.y, h3.y, acc[3]);
            acc[4]  = fma2(w1.x, h0.x, acc[4]);   acc[4]  = fma2(w1.y, h0.y, acc[4]);
            acc[5]  = fma2(w1.x, h1.x, acc[5]);   acc[5]  = fma2(w1.y, h1.y, acc[5]);
            acc[6]  = fma2(w1.x, h2.x, acc[6]);   acc[6]  = fma2(w1.y, h2.y, acc[6]);
            acc[7]  = fma2(w1.x, h3.x, acc[7]);   acc[7]  = fma2(w1.y, h3.y, acc[7]);
            acc[8]  = fma2(w2.x, h0.x, acc[8]);   acc[8]  = fma2(w2.y, h0.y, acc[8]);
            acc[9]  = fma2(w2.x, h1.x, acc[9]);   acc[9]  = fma2(w2.y, h1.y, acc[9]);
            acc[10] = fma2(w2.x, h2.x, acc[10]);  acc[10] = fma2(w2.y, h2.y, acc[10]);
            acc[11] = fma2(w2.x, h3.x, acc[11]);  acc[11] = fma2(w2.y, h3.y, acc[11]);
            acc[12] = fma2(w3.x, h0.x, acc[12]);  acc[12] = fma2(w3.y, h0.y, acc[12]);
            acc[13] = fma2(w3.x, h1.x, acc[13]);  acc[13] = fma2(w3.y, h1.y, acc[13]);
            acc[14] = fma2(w3.x, h2.x, acc[14]);  acc[14] = fma2(w3.y, h2.y, acc[14]);
            acc[15] = fma2(w3.x, h3.x, acc[15]);  acc[15] = fma2(w3.y, h3.y, acc[15]);
        }
        float f[16];
#pragma unroll
        for (int x = 0; x < 16; ++x) { float2 v = unpack2(acc[x]); f[x] = v.x + v.y; }
#pragma unroll
        for (int x = 0; x < 16; ++x) f[x] += __shfl_xor_sync(0xffffffffu, f[x], 4);
#pragma unroll
        for (int x = 0; x < 16; ++x) f[x] += __shfl_xor_sync(0xffffffffu, f[x], 8);

        float g[16];
        if (ks0) {
#pragma unroll
            for (int rr = 0; rr < 4; ++rr) {
                g[0 + rr]  = sigmoid_f(f[0 + rr]  + Gpre[rr].x);
                g[4 + rr]  = sigmoid_f(f[4 + rr]  + Gpre[rr].y);
                g[8 + rr]  = sigmoid_f(f[8 + rr]  + Gpre[rr].z);
                g[12 + rr] = sigmoid_f(f[12 + rr] + Gpre[rr].w);
            }
            if (isR) {
#pragma unroll
                for (int rr = 0; rr < 4; ++rr) {
                    int hx = hswz(rbase + rr, ccolb);
                    float4 ho = *(const float4*)(sm + OFF_H + hx);
                    ull lo = pack2(g[0 + rr] * ho.x, g[4 + rr]  * ho.y);
                    ull hi = pack2(g[8 + rr] * ho.z, g[12 + rr] * ho.w);
                    uint32_t la = smaddr + (uint32_t)(OFF_RH + hx) * 4;
#pragma unroll
                    for (uint32_t rk = 0; rk < CSZ; ++rk) {
                        uint32_t ra = mapa_sh(la, rk);
                        st_cluster_b64(ra, lo);
                        st_cluster_b64(ra + 8, hi);
                    }
                }
            }
        }
        CLUSTER_SYNC();   // A: RH complete everywhere; all H reads done

        // ============ phase 2 (u-warps): cand GEMV over RH; blend ===========
        if (!isR) {
            float4 Xpre[4];
            if (ks0) {
#pragma unroll
                for (int rr = 0; rr < 4; ++rr)
                    Xpre[rr] = *(const float4*)(g_Cx +
                        ((size_t)(b0 + rbase + rr) * T_ + t) * 256 + ccolb);
            }
            ull a2[16];
#pragma unroll
            for (int x = 0; x < 16; ++x) a2[x] = 0ull;
#pragma unroll
            for (int i = 0; i < 16; ++i) {
                const float* wp = wcp + i * 256;
                ulonglong2 w0 = *(const ulonglong2*)(wp);
                ulonglong2 w1 = *(const ulonglong2*)(wp + 4);
                ulonglong2 w2 = *(const ulonglong2*)(wp + 8);
                ulonglong2 w3 = *(const ulonglong2*)(wp + 12);
                const float* hp = rb + ((i * 4) ^ xorc);
                ulonglong2 h0 = *(const ulonglong2*)(hp);
                ulonglong2 h1 = *(const ulonglong2*)(hp + 256);
                ulonglong2 h2 = *(const ulonglong2*)(hp + 512);
                ulonglong2 h3 = *(const ulonglong2*)(hp + 768);
                a2[0]  = fma2(w0.x, h0.x, a2[0]);   a2[0]  = fma2(w0.y, h0.y, a2[0]);
                a2[1]  = fma2(w0.x, h1.x, a2[1]);   a2[1]  = fma2(w0.y, h1.y, a2[1]);
                a2[2]  = fma2(w0.x, h2.x, a2[2]);   a2[2]  = fma2(w0.y, h2.y, a2[2]);
                a2[3]  = fma2(w0.x, h3.x, a2[3]);   a2[3]  = fma2(w0.y, h3.y, a2[3]);
                a2[4]  = fma2(w1.x, h0.x, a2[4]);   a2[4]  = fma2(w1.y, h0.y, a2[4]);
                a2[5]  = fma2(w1.x, h1.x, a2[5]);   a2[5]  = fma2(w1.y, h1.y, a2[5]);
                a2[6]  = fma2(w1.x, h2.x, a2[6]);   a2[6]  = fma2(w1.y, h2.y, a2[6]);
                a2[7]  = fma2(w1.x, h3.x, a2[7]);   a2[7]  = fma2(w1.y, h3.y, a2[7]);
                a2[8]  = fma2(w2.x, h0.x, a2[8]);   a2[8]  = fma2(w2.y, h0.y, a2[8]);
                a2[9]  = fma2(w2.x, h1.x, a2[9]);   a2[9]  = fma2(w2.y, h1.y, a2[9]);
                a2[10] = fma2(w2.x, h2.x, a2[10]);  a2[10] = fma2(w2.y, h2.y, a2[10]);
                a2[11] = fma2(w2.x, h3.x, a2[11]);  a2[11] = fma2(w2.y, h3.y, a2[11]);
                a2[12] = fma2(w3.x, h0.x, a2[12]);  a2[12] = fma2(w3.y, h0.y, a2[12]);
                a2[13] = fma2(w3.x, h1.x, a2[13]);  a2[13] = fma2(w3.y, h1.y, a2[13]);
                a2[14] = fma2(w3.x, h2.x, a2[14]);  a2[14] = fma2(w3.y, h2.y, a2[14]);
                a2[15] = fma2(w3.x, h3.x, a2[15]);  a2[15] = fma2(w3.y, h3.y, a2[15]);
            }
            float f2[16];
#pragma unroll
            for (int x = 0; x < 16; ++x) { float2 v = unpack2(a2[x]); f2[x] = v.x + v.y; }
#pragma unroll
            for (int x = 0; x < 16; ++x) f2[x] += __shfl_xor_sync(0xffffffffu, f2[x], 4);
#pragma unroll
            for (int x = 0; x < 16; ++x) f2[x] += __shfl_xor_sync(0xffffffffu, f2[x], 8);

            if (ks0) {
#pragma unroll
                for (int rr = 0; rr < 4; ++rr) {
                    int hx = hswz(rbase + rr, ccolb);
                    float4 ho = *(const float4*)(sm + OFF_H + hx);  // old h
                    bool valid = (t < lenv[rr]);
                    float c0 = tanh_f(f2[0 + rr]  + Xpre[rr].x);
                    float c1 = tanh_f(f2[4 + rr]  + Xpre[rr].y);
                    float c2 = tanh_f(f2[8 + rr]  + Xpre[rr].z);
                    float c3 = tanh_f(f2[12 + rr] + Xpre[rr].w);
                    float n0 = g[0 + rr]  * ho.x + (1.f - g[0 + rr])  * c0;
                    float n1 = g[4 + rr]  * ho.y + (1.f - g[4 + rr])  * c1;
                    float n2 = g[8 + rr]  * ho.z + (1.f - g[8 + rr])  * c2;
                    float n3 = g[12 + rr] * ho.w + (1.f - g[12 + rr]) * c3;
                    float4 ov = valid ? make_float4(n0, n1, n2, n3)
                                      : make_float4(0.f, 0.f, 0.f, 0.f);
                    *(float4*)(out + ((size_t)(b0 + rbase + rr) * T_ + t) * 256
                               + ccolb) = ov;
                    ull lo = valid ? pack2(n0, n1) : pack2(ho.x, ho.y);
                    ull hi = valid ? pack2(n2, n3) : pack2(ho.z, ho.w);
                    uint32_t la = smaddr + (uint32_t)(OFF_H + hx) * 4;
#pragma unroll
                    for (uint32_t rk = 0; rk < CSZ; ++rk) {
                        uint32_t ra = mapa_sh(la, rk);
                        st_cluster_b64(ra, lo);
                        st_cluster_b64(ra + 8, hi);
                    }
                }
            }
        }
        CLUSTER_SYNC();   // B: new h complete everywhere; RH reads done
    }

    // zero-fill tail t in [tmax, 200): CTA c covers rows [c*4, c*4+4)
    for (int t = tmax; t < T_; ++t) {
#pragma unroll
        for (int q = 0; q < 2; ++q) {
            int cell = q * 512 + tid;            // 0..1023
            int row  = (int)c * 4 + (cell >> 8);
            int col  = cell & 255;
            out[((size_t)(b0 + row) * T_ + t) * 256 + col] = 0.f;
        }
    }
}

// ---------------------------------------------------------------------------
extern "C" void kernel_launch(void* const* d_in, const int* in_sizes, int n_in,
                              void* d_out, int out_size)
{
    const float* X  = (const float*)d_in[0];   // [512, 200, 256]
    const int*   L  = (const int*)  d_in[1];   // [512, 1]
    const float* Wg = (const float*)d_in[2];   // [512, 512]
    const float* bg = (const float*)d_in[3];   // [512]
    const float* Wc = (const float*)d_in[4];   // [512, 256]
    const float* bc = (const float*)d_in[5];   // [256]
    float* out = (float*)d_out;                // [512, 200, 256]

    // Input projections (parallel, independent of recurrence)
    gemm_precompute<<<dim3(BT_ / GBM, (2 * H_) / GBN), 256>>>(X, Wg, bg, L, 2 * H_);
    gemm_precompute<<<dim3(BT_ / GBM, H_ / GBN),       256>>>(X, Wc, bc, L, H_);

    // Sequential scan: 32 clusters x 4 CTAs, SMEM-resident weights
    cudaFuncSetAttribute(gru_recurrent,
                         cudaFuncAttributeMaxDynamicSharedMemorySize, SMEM_BYTES);
    gru_recurrent<<<NG_ * CSZ, THREADS_R, SMEM_BYTES>>>(Wg, Wc, L, out);
}